// round 3
// baseline (speedup 1.0000x reference)
#include <cuda_runtime.h>
#include <math.h>

#define NMAX   100000
#define ETOTMX 1700000

// ---------------- scratch (static device globals; no allocation) ----------
__device__ int   g_is64;
__device__ int   g_src[ETOTMX];
__device__ int   g_dst[ETOTMX];
__device__ int   g_csr[ETOTMX];
__device__ int   g_deg[NMAX];
__device__ int   g_cnt[NMAX];
__device__ int   g_rowptr[NMAX + 1];
__device__ __align__(16) float g_h[NMAX * 64];
__device__ __align__(16) float g_agg[NMAX * 64];
__device__ float g_as[NMAX];
__device__ float g_ad[NMAX];

// ---------------- dtype sniff: int64 vs int32 edge_index -------------------
// int64 little-endian with values < 2^31 has zero high words at odd int32
// positions. Random int32 node ids make 256 consecutive zeros impossible.
__global__ void detect_kernel(const int* __restrict__ ei32) {
    if (threadIdx.x == 0) {
        int ok = 1;
        for (int i = 0; i < 256; i++)
            if (ei32[2 * i + 1] != 0) { ok = 0; break; }
        g_is64 = ok;
    }
}

// ---------------- graph build ---------------------------------------------
__global__ void zero_counts_kernel(int nN) {
    int i = blockIdx.x * blockDim.x + threadIdx.x;
    if (i < nN) { g_deg[i] = 0; g_cnt[i] = 0; }
}

__global__ void build_edges_kernel(const void* __restrict__ ei, int E, int Etot, int nN) {
    int i = blockIdx.x * blockDim.x + threadIdx.x;
    if (i >= Etot) return;
    int s, d;
    if (i < E) {
        if (g_is64) {
            const long long* p = (const long long*)ei;
            s = (int)p[i]; d = (int)p[E + i];
        } else {
            const int* p = (const int*)ei;
            s = p[i]; d = p[E + i];
        }
        // clamp: any mis-parse becomes a wrong value, never a trap
        s = min(max(s, 0), nN - 1);
        d = min(max(d, 0), nN - 1);
    } else {
        s = d = i - E;                 // self loops appended
    }
    g_src[i] = s;
    g_dst[i] = d;
    atomicAdd(&g_deg[d], 1);
}

// single-block exclusive scan of g_deg -> g_rowptr
__global__ void scan_kernel(int nN) {
    __shared__ int ssum[1024];
    int tid   = threadIdx.x;
    int chunk = (nN + 1023) / 1024;
    int lo = tid * chunk;
    int hi = lo + chunk; if (hi > nN) hi = nN;
    int s = 0;
    for (int i = lo; i < hi; i++) s += g_deg[i];
    ssum[tid] = s;
    __syncthreads();
    for (int off = 1; off < 1024; off <<= 1) {
        int v = (tid >= off) ? ssum[tid - off] : 0;
        __syncthreads();
        ssum[tid] += v;
        __syncthreads();
    }
    int prefix = (tid == 0) ? 0 : ssum[tid - 1];
    for (int i = lo; i < hi; i++) { g_rowptr[i] = prefix; prefix += g_deg[i]; }
    if (tid == 1023) g_rowptr[nN] = ssum[1023];
}

__global__ void scatter_kernel(int Etot) {
    int i = blockIdx.x * blockDim.x + threadIdx.x;
    if (i >= Etot) return;
    int d   = g_dst[i];
    int pos = g_rowptr[d] + atomicAdd(&g_cnt[d], 1);
    g_csr[pos] = g_src[i];
}

// ---------------- per-layer: h = act(in) @ W ; alpha_s/alpha_d ------------
// PRE=true: input = relu(g_agg + pbias); else input = `in` arg (layer 1: x).
template <int K, int O, bool PRE>
__global__ void gemm_alpha_kernel(const float* __restrict__ in,
                                  const float* __restrict__ W,
                                  const float* __restrict__ avs,
                                  const float* __restrict__ avd,
                                  const float* __restrict__ pbias,
                                  int nN) {
    constexpr int BN  = 256 / O;           // nodes per block
    constexpr int WPN = O / 32;            // warps per node
    __shared__ float Wsh[K * O];
    __shared__ float insh[BN * K];
    __shared__ float as_sh[O], ad_sh[O];
    __shared__ float ps_sh[8], pd_sh[8];   // one partial per warp

    int tid = threadIdx.x;
    for (int i = tid; i < K * O; i += 256) Wsh[i] = W[i];
    if (tid < O) { as_sh[tid] = avs[tid]; ad_sh[tid] = avd[tid]; }

    int base = blockIdx.x * BN;
    const float* src = PRE ? g_agg : in;
    for (int i = tid; i < BN * K; i += 256) {
        int nl = i / K, k = i % K;
        int n  = base + nl;
        float v = 0.f;
        if (n < nN) {
            v = src[n * K + k];
            if (PRE) v = fmaxf(v + pbias[k], 0.f);
        }
        insh[i] = v;
    }
    __syncthreads();

    int nl = tid / O, c = tid % O;
    float acc = 0.f;
#pragma unroll
    for (int k = 0; k < K; k++) acc += insh[nl * K + k] * Wsh[k * O + c];

    int n = base + nl;
    if (n < nN) g_h[n * O + c] = acc;

    float ps = acc * as_sh[c];
    float pd = acc * ad_sh[c];
#pragma unroll
    for (int off = 16; off; off >>= 1) {
        ps += __shfl_xor_sync(0xffffffffu, ps, off);
        pd += __shfl_xor_sync(0xffffffffu, pd, off);
    }
    int warpId = tid >> 5;
    if ((tid & 31) == 0) { ps_sh[warpId] = ps; pd_sh[warpId] = pd; }
    __syncthreads();
    if (tid < BN && base + tid < nN) {
        float s = 0.f, d = 0.f;
#pragma unroll
        for (int w = 0; w < WPN; w++) {
            s += ps_sh[tid * WPN + w];
            d += pd_sh[tid * WPN + w];
        }
        g_as[base + tid] = s;
        g_ad[base + tid] = d;
    }
}

// ---------------- per-layer: softmax + weighted aggregate (warp/node) -----
template <int O>
__global__ void aggregate_kernel(int nN) {
    int warp = (blockIdx.x * blockDim.x + threadIdx.x) >> 5;
    int lane = threadIdx.x & 31;
    if (warp >= nN) return;

    int start = g_rowptr[warp];
    int end   = g_rowptr[warp + 1];
    float ad  = g_ad[warp];

    // segment max
    float m = -1e30f;
    for (int e = start + lane; e < end; e += 32) {
        int s = g_csr[e];
        float l = g_as[s] + ad;
        l = l > 0.f ? l : l * 0.2f;
        m = fmaxf(m, l);
    }
#pragma unroll
    for (int off = 16; off; off >>= 1) m = fmaxf(m, __shfl_xor_sync(0xffffffffu, m, off));

    // segment exp-sum
    float sum = 0.f;
    for (int e = start + lane; e < end; e += 32) {
        int s = g_csr[e];
        float l = g_as[s] + ad;
        l = l > 0.f ? l : l * 0.2f;
        sum += __expf(l - m);
    }
#pragma unroll
    for (int off = 16; off; off >>= 1) sum += __shfl_xor_sync(0xffffffffu, sum, off);
    float inv = 1.f / (sum + 1e-16f);

    // weighted gather-accumulate
    if (O == 32) {
        float acc = 0.f;
        for (int e = start; e < end; e++) {
            int s = g_csr[e];
            float l = g_as[s] + ad;
            l = l > 0.f ? l : l * 0.2f;
            float a = __expf(l - m) * inv;
            acc += a * g_h[s * 32 + lane];
        }
        g_agg[warp * 32 + lane] = acc;
    } else {
        float2 acc = make_float2(0.f, 0.f);
        for (int e = start; e < end; e++) {
            int s = g_csr[e];
            float l = g_as[s] + ad;
            l = l > 0.f ? l : l * 0.2f;
            float a = __expf(l - m) * inv;
            float2 hv = *reinterpret_cast<const float2*>(&g_h[s * 64 + lane * 2]);
            acc.x += a * hv.x;
            acc.y += a * hv.y;
        }
        *reinterpret_cast<float2*>(&g_agg[warp * 64 + lane * 2]) = acc;
    }
}

// ---------------- final: out = relu(g_agg + b3) @ Wl + bl -----------------
// Each block: 32 nodes x 128 output channels. Static shared only (~40.5KB).
__global__ void final_gemm_kernel(const float* __restrict__ b3,
                                  const float* __restrict__ Wl,
                                  const float* __restrict__ bl,
                                  float* __restrict__ out, int nN) {
    __shared__ __align__(16) float Wsh[64 * 128];   // 32 KB
    __shared__ __align__(16) float hsh[32 * 64];    // 8 KB
    __shared__ float blsh[128];

    int tid    = threadIdx.x;
    int cbase  = blockIdx.y * 128;      // channel split base
    int nbase  = blockIdx.x * 32;       // node tile base

    // stage Wl[:, cbase:cbase+128] -> Wsh[k*128 + c]
    for (int i = tid; i < 64 * 128; i += 256) {
        int k = i >> 7, c = i & 127;
        Wsh[i] = Wl[k * 512 + cbase + c];
    }
    if (tid < 128) blsh[tid] = bl[cbase + tid];

    // stage activated input tile
    for (int i = tid; i < 32 * 64; i += 256) {
        int n = nbase + (i >> 6);
        int k = i & 63;
        float v = 0.f;
        if (n < nN) v = fmaxf(g_agg[n * 64 + k] + b3[k], 0.f);
        hsh[i] = v;
    }
    __syncthreads();

    int cidx = tid & 31;    // channel group of 4: channels cidx*4 .. cidx*4+3
    int ridx = tid >> 5;    // 0..7; rows ridx, ridx+8, ridx+16, ridx+24

    float acc[4][4];
#pragma unroll
    for (int r = 0; r < 4; r++)
#pragma unroll
        for (int j = 0; j < 4; j++) acc[r][j] = 0.f;

#pragma unroll 8
    for (int k = 0; k < 64; k++) {
        float4 w = *reinterpret_cast<const float4*>(&Wsh[k * 128 + cidx * 4]);
#pragma unroll
        for (int r = 0; r < 4; r++) {
            float hv = hsh[(ridx + r * 8) * 64 + k];
            acc[r][0] += hv * w.x;
            acc[r][1] += hv * w.y;
            acc[r][2] += hv * w.z;
            acc[r][3] += hv * w.w;
        }
    }

#pragma unroll
    for (int r = 0; r < 4; r++) {
        int n = nbase + ridx + r * 8;
        if (n < nN) {
            float4 o;
            o.x = acc[r][0] + blsh[cidx * 4 + 0];
            o.y = acc[r][1] + blsh[cidx * 4 + 1];
            o.z = acc[r][2] + blsh[cidx * 4 + 2];
            o.w = acc[r][3] + blsh[cidx * 4 + 3];
            *reinterpret_cast<float4*>(&out[n * 512 + cbase + cidx * 4]) = o;
        }
    }
}

// ---------------- launch ----------------------------------------------------
extern "C" void kernel_launch(void* const* d_in, const int* in_sizes, int n_in,
                              void* d_out, int out_size) {
    const float* x   = (const float*)d_in[0];
    const void*  ei  = d_in[1];
    // d_in[2] = edge_attr: unused by GATConv (edge_dim=None)
    const float* W1 = (const float*)d_in[3];
    const float* as1 = (const float*)d_in[4];
    const float* ad1 = (const float*)d_in[5];
    const float* b1 = (const float*)d_in[6];
    const float* W2 = (const float*)d_in[7];
    const float* as2 = (const float*)d_in[8];
    const float* ad2 = (const float*)d_in[9];
    const float* b2 = (const float*)d_in[10];
    const float* W3 = (const float*)d_in[11];
    const float* as3 = (const float*)d_in[12];
    const float* ad3 = (const float*)d_in[13];
    const float* b3 = (const float*)d_in[14];
    const float* Wl = (const float*)d_in[15];
    const float* bl = (const float*)d_in[16];
    float* out = (float*)d_out;

    int nN   = in_sizes[0] / 128;      // 100000
    int E    = in_sizes[1] / 2;        // 1600000 (elem count same for i32/i64)
    int Etot = E + nN;                 // 1700000

    // ---- CSR build (once per launch, reused by all 3 layers) ----
    detect_kernel<<<1, 32>>>((const int*)ei);
    zero_counts_kernel<<<(nN + 255) / 256, 256>>>(nN);
    build_edges_kernel<<<(Etot + 255) / 256, 256>>>(ei, E, Etot, nN);
    scan_kernel<<<1, 1024>>>(nN);
    scatter_kernel<<<(Etot + 255) / 256, 256>>>(Etot);

    int aggBlocks = (nN * 32 + 255) / 256;

    // ---- layer 1: 128 -> 32 ----
    gemm_alpha_kernel<128, 32, false><<<(nN + 7) / 8, 256>>>(x, W1, as1, ad1, nullptr, nN);
    aggregate_kernel<32><<<aggBlocks, 256>>>(nN);

    // ---- layer 2: 32 -> 64 (input = relu(agg1 + b1)) ----
    gemm_alpha_kernel<32, 64, true><<<(nN + 3) / 4, 256>>>(nullptr, W2, as2, ad2, b1, nN);
    aggregate_kernel<64><<<aggBlocks, 256>>>(nN);

    // ---- layer 3: 64 -> 64 (input = relu(agg2 + b2)) ----
    gemm_alpha_kernel<64, 64, true><<<(nN + 3) / 4, 256>>>(nullptr, W3, as3, ad3, b2, nN);
    aggregate_kernel<64><<<aggBlocks, 256>>>(nN);

    // ---- final linear: relu(agg3 + b3) @ Wl + bl ----
    dim3 fgrid((nN + 31) / 32, 4);
    final_gemm_kernel<<<fgrid, 256>>>(b3, Wl, bl, out, nN);
}